// round 1
// baseline (speedup 1.0000x reference)
#include <cuda_runtime.h>
#include <math.h>

// Problem shape (fixed)
#define T_ 512
#define B_ 64
#define H_ 1024
#define I_ 1024
#define G3H (3 * H_)

// Scratch (device globals: allocation-free contract)
__device__ float g_gx[(size_t)T_ * B_ * G3H];   // [t*B + b][3H]
__device__ float g_hseq[(size_t)T_ * B_ * H_];  // [t*B + b][H]
__device__ float g_h0[B_ * H_];                 // zeros

// logical row r = b*T + t  <->  storage row t*B + b
__device__ __forceinline__ int rowmap(int r) {
    return ((r & (T_ - 1)) << 6) + (r >> 9);    // (r%512)*64 + r/512
}

__global__ void zero_kernel(float* __restrict__ p, int n) {
    int i = blockIdx.x * blockDim.x + threadIdx.x;
    if (i < n) p[i] = 0.0f;
}

// ---------------------------------------------------------------------------
// SGEMM-NT: C[M,N] = A[M,K] * B[N,K]^T   (A,B row-major, K contiguous)
// 128x128 block tile, BK=8, 256 threads, 8x8 per-thread microtile.
// mode 0: plain; mode 1: permute C rows via rowmap; mode 2: permute A rows.
// M,N multiples of 128; K multiple of 8 (guaranteed by shapes).
// ---------------------------------------------------------------------------
__global__ __launch_bounds__(256) void sgemm_nt(
    const float* __restrict__ A, const float* __restrict__ B,
    float* __restrict__ C, int N, int K, int mode)
{
    __shared__ float As[8][128];
    __shared__ float Bs[8][128];

    const int tid = threadIdx.x;
    const int r0 = blockIdx.y * 128;
    const int c0 = blockIdx.x * 128;

    const int lrow = tid >> 1;          // 0..127
    const int lq   = (tid & 1) * 4;     // 0 or 4

    int arow = r0 + lrow;
    if (mode == 2) arow = rowmap(arow);
    const float* Aptr = A + (size_t)arow * K + lq;
    const float* Bptr = B + (size_t)(c0 + lrow) * K + lq;

    const int mm = (tid >> 4) << 3;     // 0,8,...,120
    const int nn = (tid & 15) << 3;     // 0,8,...,120

    float acc[8][8];
#pragma unroll
    for (int i = 0; i < 8; ++i)
#pragma unroll
        for (int j = 0; j < 8; ++j) acc[i][j] = 0.0f;

    for (int k0 = 0; k0 < K; k0 += 8) {
        const float4 av = *(const float4*)(Aptr + k0);
        const float4 bv = *(const float4*)(Bptr + k0);
        __syncthreads();   // previous tile's reads complete before overwrite
        As[lq + 0][lrow] = av.x; As[lq + 1][lrow] = av.y;
        As[lq + 2][lrow] = av.z; As[lq + 3][lrow] = av.w;
        Bs[lq + 0][lrow] = bv.x; Bs[lq + 1][lrow] = bv.y;
        Bs[lq + 2][lrow] = bv.z; Bs[lq + 3][lrow] = bv.w;
        __syncthreads();

#pragma unroll
        for (int k = 0; k < 8; ++k) {
            const float4 a0 = *(const float4*)&As[k][mm];
            const float4 a1 = *(const float4*)&As[k][mm + 4];
            const float4 b0 = *(const float4*)&Bs[k][nn];
            const float4 b1 = *(const float4*)&Bs[k][nn + 4];
            const float a[8] = {a0.x, a0.y, a0.z, a0.w, a1.x, a1.y, a1.z, a1.w};
            const float b[8] = {b0.x, b0.y, b0.z, b0.w, b1.x, b1.y, b1.z, b1.w};
#pragma unroll
            for (int i = 0; i < 8; ++i)
#pragma unroll
                for (int j = 0; j < 8; ++j)
                    acc[i][j] = fmaf(a[i], b[j], acc[i][j]);
        }
    }

#pragma unroll
    for (int i = 0; i < 8; ++i) {
        int crow = r0 + mm + i;
        if (mode == 1) crow = rowmap(crow);
        float4* cp = (float4*)(C + (size_t)crow * N + c0 + nn);
        cp[0] = make_float4(acc[i][0], acc[i][1], acc[i][2], acc[i][3]);
        cp[1] = make_float4(acc[i][4], acc[i][5], acc[i][6], acc[i][7]);
    }
}

// ---------------------------------------------------------------------------
// Fused GRU step: block = 64 batches x 8 output cols, all 3 gates, K=1024.
// grid 128 blocks x 256 threads. Reads h_prev, writes h_out (no aliasing).
// ---------------------------------------------------------------------------
__global__ __launch_bounds__(256) void gru_step(
    const float* __restrict__ h_prev,   // [64][1024]
    const float* __restrict__ gx_t,     // [64][3072]
    const float* __restrict__ w_hh,     // [3072][1024]
    float* __restrict__ h_out)          // [64][1024]
{
    __shared__ float hs[32][64];        // [k][b]
    __shared__ float ws[3 * 8 * 32];    // [(g*8+j)*32 + k]

    const int tid = threadIdx.x;
    const int n0 = blockIdx.x * 8;
    const int b  = tid & 63;
    const int jj = tid >> 6;            // 0..3; this thread owns cols jj, jj+4

    float acc[3][2] = {{0.f, 0.f}, {0.f, 0.f}, {0.f, 0.f}};

    for (int k0 = 0; k0 < H_; k0 += 32) {
        __syncthreads();
#pragma unroll
        for (int i = tid; i < 64 * 32; i += 256) {
            const int bl = i >> 5, kl = i & 31;
            hs[kl][bl] = h_prev[bl * H_ + k0 + kl];
        }
#pragma unroll
        for (int i = tid; i < 768; i += 256) {
            const int gj = i >> 5, kl = i & 31;
            const int g = gj >> 3, j = gj & 7;
            ws[gj * 32 + kl] = w_hh[(size_t)(g * H_ + n0 + j) * H_ + k0 + kl];
        }
        __syncthreads();

#pragma unroll
        for (int kk = 0; kk < 32; kk += 4) {
            const float a0 = hs[kk + 0][b];
            const float a1 = hs[kk + 1][b];
            const float a2 = hs[kk + 2][b];
            const float a3 = hs[kk + 3][b];
#pragma unroll
            for (int g = 0; g < 3; ++g) {
                const float4 w0 = *(const float4*)&ws[(g * 8 + jj) * 32 + kk];
                const float4 w1 = *(const float4*)&ws[(g * 8 + jj + 4) * 32 + kk];
                acc[g][0] = fmaf(a0, w0.x, fmaf(a1, w0.y, fmaf(a2, w0.z, fmaf(a3, w0.w, acc[g][0]))));
                acc[g][1] = fmaf(a0, w1.x, fmaf(a1, w1.y, fmaf(a2, w1.z, fmaf(a3, w1.w, acc[g][1]))));
            }
        }
    }

#pragma unroll
    for (int p = 0; p < 2; ++p) {
        const int jg = n0 + jj + p * 4;
        const float gr = gx_t[b * G3H + jg]            + acc[0][p];
        const float gz = gx_t[b * G3H + H_ + jg]       + acc[1][p];
        const float gn = gx_t[b * G3H + 2 * H_ + jg];
        const float r = 1.0f / (1.0f + expf(-gr));
        const float z = 1.0f / (1.0f + expf(-gz));
        const float n = tanhf(gn + r * acc[2][p]);
        const float hold = h_prev[b * H_ + jg];
        h_out[b * H_ + jg] = (1.0f - z) * n + z * hold;
    }
}

// ---------------------------------------------------------------------------
// kernel_launch: 1 zero + 1 big GEMM + 512 step kernels + 1 big GEMM.
// Graph-capturable: kernel launches only, no allocs, no syncs.
// Inputs (metadata order): x[64,512,1024], w_ih[3072,1024],
//                          w_hh[3072,1024], w_proj[1024,1024]. Output fp32.
// ---------------------------------------------------------------------------
extern "C" void kernel_launch(void* const* d_in, const int* in_sizes, int n_in,
                              void* d_out, int out_size) {
    const float* x      = (const float*)d_in[0];
    const float* w_ih   = (const float*)d_in[1];
    const float* w_hh   = (const float*)d_in[2];
    const float* w_proj = (const float*)d_in[3];
    float* out = (float*)d_out;

    float *gx, *hseq, *h0;
    cudaGetSymbolAddress((void**)&gx,   g_gx);
    cudaGetSymbolAddress((void**)&hseq, g_hseq);
    cudaGetSymbolAddress((void**)&h0,   g_h0);

    // h0 = 0 (defensive; also statically zero)
    zero_kernel<<<(B_ * H_ + 255) / 256, 256>>>(h0, B_ * H_);

    // Phase 1: gx[t*B+b][3H] = x @ w_ih^T  (mode 1: permute C rows)
    {
        dim3 grid(G3H / 128, (B_ * T_) / 128);
        sgemm_nt<<<grid, 256>>>(x, w_ih, gx, G3H, I_, 1);
    }

    // Phase 2: 512 sequential fused GRU steps
    for (int t = 0; t < T_; ++t) {
        const float* hp = (t == 0) ? h0 : (hseq + (size_t)(t - 1) * B_ * H_);
        gru_step<<<128, 256>>>(hp,
                               gx + (size_t)t * B_ * G3H,
                               w_hh,
                               hseq + (size_t)t * B_ * H_);
    }

    // Phase 3: out[b*T+t][H] = hs @ w_proj^T  (mode 2: permute A rows)
    {
        dim3 grid(H_ / 128, (B_ * T_) / 128);
        sgemm_nt<<<grid, 256>>>(hseq, w_proj, out, H_, H_, 2);
    }
}

// round 3
// speedup vs baseline: 2.6080x; 2.6080x over previous
#include <cuda_runtime.h>
#include <math.h>

// Problem shape (fixed)
#define T_ 512
#define B_ 64
#define H_ 1024
#define I_ 1024
#define G3H 3072
#define KSPLIT 6
#define NBLK 24                       // n-blocks of 128 cols
#define GRID_P (NBLK * KSPLIT)        // 144 persistent blocks
#define WS_ELEMS (176 * 128)          // max k-slice (176) x 128 cols
#define SMEM_BYTES ((WS_ELEMS + 16 * 64) * 4)

// Scratch (device globals: allocation-free contract)
__device__ float g_gx[(size_t)T_ * B_ * G3H];      // [t][b][3H]
__device__ float g_hseqT[(size_t)T_ * H_ * B_];    // [t][k][b]
__device__ float g_h0[H_ * B_];                    // zeros ([k][b])
__device__ float g_gh6[(size_t)KSPLIT * G3H * B_]; // [s][n][b] split-K partials
__device__ unsigned int g_bar;                     // grid barrier counter

// packed fp32x2 FMA: acc += a * b (elementwise, exact fp32 per lane)
#define FMA2(acc, a, b) \
    asm("fma.rn.f32x2 %0, %1, %2, %0;" : "+l"(acc) : "l"(a), "l"(b))
#define PACK2(d, x) \
    asm("mov.b64 %0, {%1, %1};" : "=l"(d) : "f"(x))

__device__ __forceinline__ void unpack2(unsigned long long v, float& x, float& y) {
    asm("mov.b64 {%0, %1}, %2;" : "=f"(x), "=f"(y) : "l"(v));
}

// logical row r = b*T + t  <->  storage row t*B + b (phase-1 gx layout)
__device__ __forceinline__ int rowmap(int r) {
    return ((r & (T_ - 1)) << 6) + (r >> 9);
}

__global__ void init_kernel(float* __restrict__ h0) {
    int i = blockIdx.x * blockDim.x + threadIdx.x;
    if (i < H_ * B_) h0[i] = 0.0f;
    if (i == 0) g_bar = 0u;
}

// ---------------------------------------------------------------------------
// Phase-1 SGEMM-NT (known good): gx[t*B+b][3H] = x @ w_ih^T   (mode 1)
// ---------------------------------------------------------------------------
__global__ __launch_bounds__(256) void sgemm_nt(
    const float* __restrict__ A, const float* __restrict__ B,
    float* __restrict__ C, int N, int K, int mode)
{
    __shared__ float As[8][128];
    __shared__ float Bs[8][128];

    const int tid = threadIdx.x;
    const int r0 = blockIdx.y * 128;
    const int c0 = blockIdx.x * 128;

    const int lrow = tid >> 1;
    const int lq   = (tid & 1) * 4;

    int arow = r0 + lrow;
    if (mode == 2) arow = rowmap(arow);
    const float* Aptr = A + (size_t)arow * K + lq;
    const float* Bptr = B + (size_t)(c0 + lrow) * K + lq;

    const int mm = (tid >> 4) << 3;
    const int nn = (tid & 15) << 3;

    float acc[8][8];
#pragma unroll
    for (int i = 0; i < 8; ++i)
#pragma unroll
        for (int j = 0; j < 8; ++j) acc[i][j] = 0.0f;

    for (int k0 = 0; k0 < K; k0 += 8) {
        const float4 av = *(const float4*)(Aptr + k0);
        const float4 bv = *(const float4*)(Bptr + k0);
        __syncthreads();
        As[lq + 0][lrow] = av.x; As[lq + 1][lrow] = av.y;
        As[lq + 2][lrow] = av.z; As[lq + 3][lrow] = av.w;
        Bs[lq + 0][lrow] = bv.x; Bs[lq + 1][lrow] = bv.y;
        Bs[lq + 2][lrow] = bv.z; Bs[lq + 3][lrow] = bv.w;
        __syncthreads();

#pragma unroll
        for (int k = 0; k < 8; ++k) {
            const float4 a0 = *(const float4*)&As[k][mm];
            const float4 a1 = *(const float4*)&As[k][mm + 4];
            const float4 b0 = *(const float4*)&Bs[k][nn];
            const float4 b1 = *(const float4*)&Bs[k][nn + 4];
            const float a[8] = {a0.x, a0.y, a0.z, a0.w, a1.x, a1.y, a1.z, a1.w};
            const float b[8] = {b0.x, b0.y, b0.z, b0.w, b1.x, b1.y, b1.z, b1.w};
#pragma unroll
            for (int i = 0; i < 8; ++i)
#pragma unroll
                for (int j = 0; j < 8; ++j)
                    acc[i][j] = fmaf(a[i], b[j], acc[i][j]);
        }
    }

#pragma unroll
    for (int i = 0; i < 8; ++i) {
        int crow = r0 + mm + i;
        if (mode == 1) crow = rowmap(crow);
        float4* cp = (float4*)(C + (size_t)crow * N + c0 + nn);
        cp[0] = make_float4(acc[i][0], acc[i][1], acc[i][2], acc[i][3]);
        cp[1] = make_float4(acc[i][4], acc[i][5], acc[i][6], acc[i][7]);
    }
}

// ---------------------------------------------------------------------------
// Persistent recurrence: 144 blocks co-resident (1/SM guaranteed), 512 steps,
// 2 grid barriers per step. w_hh slice lives in smem for the whole kernel.
// ---------------------------------------------------------------------------
__device__ __forceinline__ void grid_barrier(unsigned int target) {
    __syncthreads();
    if (threadIdx.x == 0) {
        __threadfence();
        atomicAdd(&g_bar, 1u);
        while (*((volatile unsigned int*)&g_bar) < target) { }
        __threadfence();
    }
    __syncthreads();
}

extern __shared__ float dynsmem[];

__global__ __launch_bounds__(256) void gru_persistent(
    const float* __restrict__ h0,      // [1024][64] zeros
    float* __restrict__ hseqT,         // [512][1024][64]
    const float* __restrict__ gx,      // [512][64][3072]
    const float* __restrict__ w_hh,    // [3072][1024]
    float* __restrict__ gh6)           // [6][3072][64]
{
    float* ws = dynsmem;               // [kk][j] kk<176 (k-major), j<128
    float* hs = dynsmem + WS_ELEMS;    // [16][64]

    const int tid = threadIdx.x;
    const int bid = blockIdx.x;
    const int nbk = bid % NBLK;        // 0..23
    const int s   = bid / NBLK;        // 0..5
    const int n0  = nbk * 128;
    const int kbase = (s < 4) ? s * 176 : 704 + (s - 4) * 160;
    const int klen  = (s < 4) ? 176 : 160;
    const int nkt   = klen >> 4;

    // One-time: stage w slice (k-major, scalar) into smem.
    // i = j*klen + kk -> consecutive lanes read consecutive k (coalesced LDG).
    for (int i = tid; i < klen * 128; i += 256) {
        const int j  = i / klen;
        const int kk = i - j * klen;
        ws[kk * 128 + j] = w_hh[(size_t)(n0 + j) * 1024 + kbase + kk];
    }
    __syncthreads();

    const int bg  = tid >> 5;          // warp id: batches bg*8..+7
    const int ng  = tid & 31;          // lane:    cols n0 + ng*4..+3
    const int h_kl = tid >> 4;         // staging: row kl, 4 cols
    const int h_c  = (tid & 15) * 4;

    unsigned int barcnt = 0;

    for (int t = 0; t < T_; ++t) {
        const float* hT = (t == 0) ? h0 : (hseqT + (size_t)(t - 1) * H_ * B_);

        // ---- split-K gemm: gh6[s][n][b] = sum_{k in slice} w[n][k]*h[k][b]
        unsigned long long acc[4][4];
#pragma unroll
        for (int p = 0; p < 4; ++p)
#pragma unroll
            for (int c = 0; c < 4; ++c) acc[p][c] = 0ull;

        float4 hv = *(const float4*)&hT[(size_t)(kbase + h_kl) * 64 + h_c];

        for (int kt = 0; kt < nkt; ++kt) {
            __syncthreads();
            *(float4*)&hs[h_kl * 64 + h_c] = hv;
            __syncthreads();
            if (kt + 1 < nkt)
                hv = *(const float4*)&hT[(size_t)(kbase + (kt + 1) * 16 + h_kl) * 64 + h_c];

#pragma unroll
            for (int k = 0; k < 16; ++k) {
                const float4 wv = *(const float4*)&ws[(kt * 16 + k) * 128 + ng * 4];
                unsigned long long W0, W1, W2, W3;
                PACK2(W0, wv.x); PACK2(W1, wv.y); PACK2(W2, wv.z); PACK2(W3, wv.w);
                const ulonglong2 A01 = *(const ulonglong2*)&hs[k * 64 + bg * 8];
                const ulonglong2 A23 = *(const ulonglong2*)&hs[k * 64 + bg * 8 + 4];
                FMA2(acc[0][0], A01.x, W0); FMA2(acc[1][0], A01.y, W0);
                FMA2(acc[2][0], A23.x, W0); FMA2(acc[3][0], A23.y, W0);
                FMA2(acc[0][1], A01.x, W1); FMA2(acc[1][1], A01.y, W1);
                FMA2(acc[2][1], A23.x, W1); FMA2(acc[3][1], A23.y, W1);
                FMA2(acc[0][2], A01.x, W2); FMA2(acc[1][2], A01.y, W2);
                FMA2(acc[2][2], A23.x, W2); FMA2(acc[3][2], A23.y, W2);
                FMA2(acc[0][3], A01.x, W3); FMA2(acc[1][3], A01.y, W3);
                FMA2(acc[2][3], A23.x, W3); FMA2(acc[3][3], A23.y, W3);
            }
        }

        {
            float* outp = gh6 + ((size_t)s * G3H + n0 + ng * 4) * 64 + bg * 8;
#pragma unroll
            for (int c = 0; c < 4; ++c) {
                ulonglong2 v0, v1;
                v0.x = acc[0][c]; v0.y = acc[1][c];
                v1.x = acc[2][c]; v1.y = acc[3][c];
                *(ulonglong2*)(outp + (size_t)c * 64)     = v0;
                *(ulonglong2*)(outp + (size_t)c * 64 + 4) = v1;
            }
        }

        grid_barrier(++barcnt * GRID_P);

        // ---- gate epilogue (distributed across all 144 blocks)
        {
            const float* gxt = gx + (size_t)t * B_ * G3H;
            float* hOut = hseqT + (size_t)t * H_ * B_;
            for (int e = bid * 256 + tid; e < H_ * B_; e += GRID_P * 256) {
                const int b = e & 63;
                const int j = e >> 6;
                float sr = 0.f, sz = 0.f, sn = 0.f;
#pragma unroll
                for (int ss = 0; ss < KSPLIT; ++ss) {
                    const float* p = gh6 + (size_t)ss * G3H * 64;
                    sr += __ldcg(&p[(size_t)j * 64 + b]);
                    sz += __ldcg(&p[(size_t)(1024 + j) * 64 + b]);
                    sn += __ldcg(&p[(size_t)(2048 + j) * 64 + b]);
                }
                const float gr = gxt[(size_t)b * G3H + j] + sr;
                const float gz = gxt[(size_t)b * G3H + 1024 + j] + sz;
                const float gn = gxt[(size_t)b * G3H + 2048 + j];
                const float r = 1.0f / (1.0f + expf(-gr));
                const float z = 1.0f / (1.0f + expf(-gz));
                const float n = tanhf(gn + r * sn);
                const float hp = hT[(size_t)j * 64 + b];
                hOut[(size_t)j * 64 + b] = (1.0f - z) * n + z * hp;
            }
        }

        grid_barrier(++barcnt * GRID_P);
    }
}

// ---------------------------------------------------------------------------
// Phase-3 projection (packed f32x2): out[b][t][n] = sum_k hseqT[t][k][b]*wp[n][k]
// ---------------------------------------------------------------------------
__global__ __launch_bounds__(256) void proj_gemm(
    const float* __restrict__ hseqT,
    const float* __restrict__ wp,
    float* __restrict__ out)
{
    __shared__ float  hsm[16][64];
    __shared__ float2 ws2[16][128];

    const int tid = threadIdx.x;
    const int n0  = blockIdx.x * 128;
    const int t   = blockIdx.y;
    const float* hT = hseqT + (size_t)t * H_ * B_;

    const int bg = tid >> 5;
    const int ng = tid & 31;
    const int h_kl = tid >> 4;
    const int h_c  = (tid & 15) * 4;
    const int w_j  = tid >> 1;
    const int w_kq = (tid & 1) * 8;

    unsigned long long acc[4][4];
#pragma unroll
    for (int p = 0; p < 4; ++p)
#pragma unroll
        for (int c = 0; c < 4; ++c) acc[p][c] = 0ull;

    const float* wrow = wp + (size_t)(n0 + w_j) * 1024 + w_kq;

    for (int k0 = 0; k0 < H_; k0 += 16) {
        const float4 hv  = *(const float4*)&hT[(size_t)(k0 + h_kl) * 64 + h_c];
        const float4 wv0 = *(const float4*)&wrow[k0];
        const float4 wv1 = *(const float4*)&wrow[k0 + 4];
        __syncthreads();
        *(float4*)&hsm[h_kl][h_c] = hv;
        ws2[w_kq + 0][w_j] = make_float2(wv0.x, wv0.x);
        ws2[w_kq + 1][w_j] = make_float2(wv0.y, wv0.y);
        ws2[w_kq + 2][w_j] = make_float2(wv0.z, wv0.z);
        ws2[w_kq + 3][w_j] = make_float2(wv0.w, wv0.w);
        ws2[w_kq + 4][w_j] = make_float2(wv1.x, wv1.x);
        ws2[w_kq + 5][w_j] = make_float2(wv1.y, wv1.y);
        ws2[w_kq + 6][w_j] = make_float2(wv1.z, wv1.z);
        ws2[w_kq + 7][w_j] = make_float2(wv1.w, wv1.w);
        __syncthreads();

#pragma unroll
        for (int k = 0; k < 16; ++k) {
            const ulonglong2 A01 = *(const ulonglong2*)&hsm[k][bg * 8];
            const ulonglong2 A23 = *(const ulonglong2*)&hsm[k][bg * 8 + 4];
            const ulonglong2 W01 = *(const ulonglong2*)&ws2[k][ng * 4];
            const ulonglong2 W23 = *(const ulonglong2*)&ws2[k][ng * 4 + 2];
            FMA2(acc[0][0], A01.x, W01.x); FMA2(acc[1][0], A01.y, W01.x);
            FMA2(acc[2][0], A23.x, W01.x); FMA2(acc[3][0], A23.y, W01.x);
            FMA2(acc[0][1], A01.x, W01.y); FMA2(acc[1][1], A01.y, W01.y);
            FMA2(acc[2][1], A23.x, W01.y); FMA2(acc[3][1], A23.y, W01.y);
            FMA2(acc[0][2], A01.x, W23.x); FMA2(acc[1][2], A01.y, W23.x);
            FMA2(acc[2][2], A23.x, W23.x); FMA2(acc[3][2], A23.y, W23.x);
            FMA2(acc[0][3], A01.x, W23.y); FMA2(acc[1][3], A01.y, W23.y);
            FMA2(acc[2][3], A23.x, W23.y); FMA2(acc[3][3], A23.y, W23.y);
        }
    }

#pragma unroll
    for (int p = 0; p < 4; ++p) {
        const int b = bg * 8 + 2 * p;
#pragma unroll
        for (int c = 0; c < 4; ++c) {
            float x, y;
            unpack2(acc[p][c], x, y);
            const int n = n0 + ng * 4 + c;
            out[((size_t)b * T_ + t) * H_ + n]       = x;
            out[((size_t)(b + 1) * T_ + t) * H_ + n] = y;
        }
    }
}

// ---------------------------------------------------------------------------
// kernel_launch — 4 graph nodes total, graph-capturable, allocation-free.
// ---------------------------------------------------------------------------
extern "C" void kernel_launch(void* const* d_in, const int* in_sizes, int n_in,
                              void* d_out, int out_size) {
    const float* x      = (const float*)d_in[0];
    const float* w_ih   = (const float*)d_in[1];
    const float* w_hh   = (const float*)d_in[2];
    const float* w_proj = (const float*)d_in[3];
    float* out = (float*)d_out;

    float *gx, *hseqT, *h0, *gh6;
    cudaGetSymbolAddress((void**)&gx,    g_gx);
    cudaGetSymbolAddress((void**)&hseqT, g_hseqT);
    cudaGetSymbolAddress((void**)&h0,    g_h0);
    cudaGetSymbolAddress((void**)&gh6,   g_gh6);

    cudaFuncSetAttribute(gru_persistent,
                         cudaFuncAttributeMaxDynamicSharedMemorySize, SMEM_BYTES);

    init_kernel<<<(H_ * B_ + 255) / 256, 256>>>(h0);

    // Phase 1: gx[t][b][3H] = x @ w_ih^T
    {
        dim3 grid(G3H / 128, (B_ * T_) / 128);
        sgemm_nt<<<grid, 256>>>(x, w_ih, gx, G3H, I_, 1);
    }

    // Phase 2: whole recurrence in ONE persistent kernel
    gru_persistent<<<GRID_P, 256, SMEM_BYTES>>>(h0, hseqT, gx, w_hh, gh6);

    // Phase 3: out = hs @ w_proj^T
    {
        dim3 grid(H_ / 128, T_);
        proj_gemm<<<grid, 256>>>(hseqT, w_proj, out);
    }
}

// round 5
// speedup vs baseline: 2.7618x; 1.0590x over previous
#include <cuda_runtime.h>
#include <cuda_bf16.h>
#include <math.h>
#include <stdint.h>

// Problem shape (fixed)
#define T_ 512
#define B_ 64
#define H_ 1024
#define I_ 1024
#define G3H 3072
#define NBLK 24
#define KSPLIT 6
#define GRID_P 144            // persistent CTAs (<=148, 1/SM => all resident)

// Dynamic smem byte offsets (sized for max klen=176, kpad=184)
#define SM_A_HI 0
#define SM_A_LO (128 * 184 * 2)                 // 47104
#define SM_B_HI (2 * 128 * 184 * 2)             // 94208
#define SM_B_LO (SM_B_HI + 176 * 72 * 2)        // 119552
#define SM_TOTAL (SM_B_LO + 176 * 72 * 2)       // 144896

// Scratch (device globals: allocation-free contract)
__device__ float g_gx[(size_t)T_ * G3H * B_];       // [t][n][b]
__device__ float g_hseqT[(size_t)T_ * H_ * B_];     // [t][k][b]
__device__ float g_gh[(size_t)KSPLIT * G3H * B_];   // [s][n][b]
__device__ __nv_bfloat16 g_hT_hi[H_ * B_];          // [k][b]
__device__ __nv_bfloat16 g_hT_lo[H_ * B_];          // [k][b]
__device__ unsigned int g_bar;

__device__ __forceinline__ uint32_t smem_u32(const void* p) {
    uint32_t a;
    asm("{ .reg .u64 t; cvta.to.shared.u64 t, %1; cvt.u32.u64 %0, t; }"
        : "=r"(a) : "l"(p));
    return a;
}

__device__ __forceinline__ void ldsm_x4(uint32_t* r, uint32_t addr) {
    asm volatile("ldmatrix.sync.aligned.m8n8.x4.shared.b16 {%0,%1,%2,%3}, [%4];"
                 : "=r"(r[0]), "=r"(r[1]), "=r"(r[2]), "=r"(r[3]) : "r"(addr));
}
__device__ __forceinline__ void ldsm_x4_t(uint32_t* r, uint32_t addr) {
    asm volatile("ldmatrix.sync.aligned.m8n8.x4.trans.shared.b16 {%0,%1,%2,%3}, [%4];"
                 : "=r"(r[0]), "=r"(r[1]), "=r"(r[2]), "=r"(r[3]) : "r"(addr));
}
__device__ __forceinline__ void mma_bf16(float* d, const uint32_t* a, const uint32_t* b) {
    asm volatile("mma.sync.aligned.m16n8k16.row.col.f32.bf16.bf16.f32 "
                 "{%0,%1,%2,%3}, {%4,%5,%6,%7}, {%8,%9}, {%0,%1,%2,%3};"
                 : "+f"(d[0]), "+f"(d[1]), "+f"(d[2]), "+f"(d[3])
                 : "r"(a[0]), "r"(a[1]), "r"(a[2]), "r"(a[3]), "r"(b[0]), "r"(b[1]));
}

__global__ void init_kernel() {
    int i = blockIdx.x * blockDim.x + threadIdx.x;
    if (i < H_ * B_ / 2) {
        ((uint32_t*)g_hT_hi)[i] = 0u;
        ((uint32_t*)g_hT_lo)[i] = 0u;
    }
    if (i == 0) g_bar = 0u;
}

// ---------------------------------------------------------------------------
// Phase-1 SGEMM-NT with scatter epilogue: gx[t][n][b] = x @ w_ih^T
// A rows r = b*T + t (x layout [b][t][i]).
// ---------------------------------------------------------------------------
__global__ __launch_bounds__(256) void sgemm_gx(
    const float* __restrict__ A, const float* __restrict__ B,
    float* __restrict__ C, int K)
{
    __shared__ float As[8][128];
    __shared__ float Bs[8][128];

    const int tid = threadIdx.x;
    const int r0 = blockIdx.y * 128;
    const int c0 = blockIdx.x * 128;

    const int lrow = tid >> 1;
    const int lq   = (tid & 1) * 4;

    const float* Aptr = A + (size_t)(r0 + lrow) * K + lq;
    const float* Bptr = B + (size_t)(c0 + lrow) * K + lq;

    const int mm = (tid >> 4) << 3;
    const int nn = (tid & 15) << 3;

    float acc[8][8];
#pragma unroll
    for (int i = 0; i < 8; ++i)
#pragma unroll
        for (int j = 0; j < 8; ++j) acc[i][j] = 0.0f;

    for (int k0 = 0; k0 < K; k0 += 8) {
        const float4 av = *(const float4*)(Aptr + k0);
        const float4 bv = *(const float4*)(Bptr + k0);
        __syncthreads();
        As[lq + 0][lrow] = av.x; As[lq + 1][lrow] = av.y;
        As[lq + 2][lrow] = av.z; As[lq + 3][lrow] = av.w;
        Bs[lq + 0][lrow] = bv.x; Bs[lq + 1][lrow] = bv.y;
        Bs[lq + 2][lrow] = bv.z; Bs[lq + 3][lrow] = bv.w;
        __syncthreads();

#pragma unroll
        for (int k = 0; k < 8; ++k) {
            const float4 a0 = *(const float4*)&As[k][mm];
            const float4 a1 = *(const float4*)&As[k][mm + 4];
            const float4 b0 = *(const float4*)&Bs[k][nn];
            const float4 b1 = *(const float4*)&Bs[k][nn + 4];
            const float a[8] = {a0.x, a0.y, a0.z, a0.w, a1.x, a1.y, a1.z, a1.w};
            const float b[8] = {b0.x, b0.y, b0.z, b0.w, b1.x, b1.y, b1.z, b1.w};
#pragma unroll
            for (int i = 0; i < 8; ++i)
#pragma unroll
                for (int j = 0; j < 8; ++j)
                    acc[i][j] = fmaf(a[i], b[j], acc[i][j]);
        }
    }

    // scatter: C[t][n][b], where A row r = b*T + t
#pragma unroll
    for (int i = 0; i < 8; ++i) {
        const int r = r0 + mm + i;
        const int b = r >> 9;
        const int t = r & (T_ - 1);
#pragma unroll
        for (int j = 0; j < 8; ++j) {
            const int n = c0 + nn + j;
            C[((size_t)t * G3H + n) * B_ + b] = acc[i][j];
        }
    }
}

// ---------------------------------------------------------------------------
// Persistent bf16-MMA recurrence: 144 CTAs, 512 steps, hi/lo split (3 HMMA
// passes, fp32 register accumulate). W slice resident in smem for all steps.
// ---------------------------------------------------------------------------
__device__ __forceinline__ void grid_barrier(unsigned int target) {
    __syncthreads();
    if (threadIdx.x == 0) {
        __threadfence();
        atomicAdd(&g_bar, 1u);
        while (*((volatile unsigned int*)&g_bar) < target) { }
        __threadfence();
    }
    __syncthreads();
}

extern __shared__ char dynsm[];

__global__ __launch_bounds__(256) void gru_persistent(
    const float* __restrict__ w_hh)   // [3072][1024]
{
    char* sm = dynsm;
    const uint32_t smem_base = smem_u32(sm);
    const int tid = threadIdx.x;
    const int wid = tid >> 5;
    const int lid = tid & 31;
    const int bid = blockIdx.x;
    const int nbk = bid % NBLK;
    const int s   = bid / NBLK;
    const int n0  = nbk * 128;
    const int kbase = (s < 4) ? s * 176 : 704 + (s - 4) * 160;
    const int klen  = (s < 4) ? 176 : 160;
    const int nkt   = klen >> 4;
    const int kpad  = klen + 8;

    // One-time: stage W slice hi/lo, rows padded to kpad (bank-spread for LDSM)
    {
        __nv_bfloat16* wsH = (__nv_bfloat16*)(sm + SM_A_HI);
        __nv_bfloat16* wsL = (__nv_bfloat16*)(sm + SM_A_LO);
        for (int i = tid; i < 128 * klen; i += 256) {
            const int row = i / klen;
            const int k   = i - row * klen;
            const float w = w_hh[(size_t)(n0 + row) * H_ + kbase + k];
            const __nv_bfloat16 hi = __float2bfloat16(w);
            wsH[row * kpad + k] = hi;
            wsL[row * kpad + k] = __float2bfloat16(w - __bfloat162float(hi));
        }
    }

    // Warp tiling: wn in 0..3 (32 n rows), wb in 0..1 (32 b cols)
    const int wn = wid >> 1;
    const int wb = wid & 1;

    // ldmatrix per-lane addresses
    // A (non-trans): lanes 0-7 rows g, 8-15 rows g+8, 16-31 same rows k+8
    const uint32_t aAddr0 = smem_base + SM_A_HI +
        (uint32_t)(((wn * 32 + (lid & 15)) * kpad + ((lid >> 4) << 3)) << 1);
    // B (trans): k = (l&7) + ((l>>3)&1)*8, b = wb*32 + ((l>>4)&1)*8
    const uint32_t bAddr0 = smem_base + SM_B_HI +
        (uint32_t)(((((lid >> 3) & 1) * 8 + (lid & 7)) * 72 + wb * 32 + ((lid >> 4) << 3)) << 1);

    const uint32_t A_LO_OFF = SM_A_LO - SM_A_HI;
    const uint32_t B_LO_OFF = SM_B_LO - SM_B_HI;
    const uint32_t aMOff = (uint32_t)(16 * kpad * 2);   // second m16 tile

    __nv_bfloat16* hsH = (__nv_bfloat16*)(sm + SM_B_HI);
    __nv_bfloat16* hsL = (__nv_bfloat16*)(sm + SM_B_LO);

    unsigned int barcnt = 0;

    for (int t = 0; t < T_; ++t) {
        // ---- stage h_{t-1} slice [klen][64] hi/lo into padded [k][72] smem
        __syncthreads();   // prior LDSM reads complete before overwrite
        for (int i = tid; i < klen * 32; i += 256) {
            const int k  = i >> 5;
            const int bp = (i & 31) << 1;
            const uint32_t vh = __ldcg((const uint32_t*)(g_hT_hi + (size_t)(kbase + k) * B_ + bp));
            const uint32_t vl = __ldcg((const uint32_t*)(g_hT_lo + (size_t)(kbase + k) * B_ + bp));
            *(uint32_t*)&hsH[k * 72 + bp] = vh;
            *(uint32_t*)&hsL[k * 72 + bp] = vl;
        }
        __syncthreads();

        // ---- mainloop: 3 HMMA passes per k16 chunk
        float d[2][4][4];
#pragma unroll
        for (int m = 0; m < 2; ++m)
#pragma unroll
            for (int nt = 0; nt < 4; ++nt)
#pragma unroll
                for (int q = 0; q < 4; ++q) d[m][nt][q] = 0.0f;

        for (int kc = 0; kc < nkt; ++kc) {
            uint32_t aH0[4], aH1[4], aL0[4], aL1[4], bh[8], bl[8];
            const uint32_t aA = aAddr0 + (uint32_t)(kc * 32);
            const uint32_t bA = bAddr0 + (uint32_t)(kc * 2304);
            ldsm_x4(aH0, aA);
            ldsm_x4(aH1, aA + aMOff);
            ldsm_x4(aL0, aA + A_LO_OFF);
            ldsm_x4(aL1, aA + A_LO_OFF + aMOff);
            ldsm_x4_t(bh,     bA);
            ldsm_x4_t(bh + 4, bA + 32);
            ldsm_x4_t(bl,     bA + B_LO_OFF);
            ldsm_x4_t(bl + 4, bA + B_LO_OFF + 32);

#pragma unroll
            for (int m = 0; m < 2; ++m)
#pragma unroll
                for (int nt = 0; nt < 4; ++nt)
                    mma_bf16(d[m][nt], m ? aH1 : aH0, &bh[nt * 2]);
#pragma unroll
            for (int m = 0; m < 2; ++m)
#pragma unroll
                for (int nt = 0; nt < 4; ++nt)
                    mma_bf16(d[m][nt], m ? aH1 : aH0, &bl[nt * 2]);
#pragma unroll
            for (int m = 0; m < 2; ++m)
#pragma unroll
                for (int nt = 0; nt < 4; ++nt)
                    mma_bf16(d[m][nt], m ? aL1 : aL0, &bh[nt * 2]);
        }

        // ---- epilogue: D(n,b) -> g_gh[s][n][b]  (float2, b pairs contiguous)
        {
            float* gh = g_gh + (size_t)s * G3H * B_;
            const int g = lid >> 2;
            const int q = lid & 3;
#pragma unroll
            for (int m = 0; m < 2; ++m)
#pragma unroll
                for (int nt = 0; nt < 4; ++nt) {
                    const int n = n0 + wn * 32 + m * 16 + g;
                    const int b = wb * 32 + nt * 8 + q * 2;
                    *(float2*)&gh[(size_t)n * B_ + b] =
                        make_float2(d[m][nt][0], d[m][nt][1]);
                    *(float2*)&gh[(size_t)(n + 8) * B_ + b] =
                        make_float2(d[m][nt][2], d[m][nt][3]);
                }
        }

        grid_barrier(++barcnt * GRID_P);

        // ---- gate epilogue (b-fast: all accesses coalesced)
        {
            const float* gxt = g_gx + (size_t)t * G3H * B_;
            for (int e = bid * 256 + tid; e < B_ * H_; e += GRID_P * 256) {
                const int b = e & 63;
                const int j = e >> 6;
                float sr = 0.f, sz = 0.f, sn = 0.f;
#pragma unroll
                for (int ss = 0; ss < KSPLIT; ++ss) {
                    const float* p = g_gh + (size_t)ss * G3H * B_;
                    sr += __ldcg(p + (size_t)j * B_ + b);
                    sz += __ldcg(p + (size_t)(1024 + j) * B_ + b);
                    sn += __ldcg(p + (size_t)(2048 + j) * B_ + b);
                }
                const float gr = gxt[(size_t)j * B_ + b] + sr;
                const float gz = gxt[(size_t)(1024 + j) * B_ + b] + sz;
                const float gn = gxt[(size_t)(2048 + j) * B_ + b];
                const float r = 1.0f / (1.0f + expf(-gr));
                const float z = 1.0f / (1.0f + expf(-gz));
                const float n = tanhf(gn + r * sn);
                const float hp = (t == 0) ? 0.0f
                               : g_hseqT[((size_t)(t - 1) * H_ + j) * B_ + b];
                const float h = (1.0f - z) * n + z * hp;
                g_hseqT[((size_t)t * H_ + j) * B_ + b] = h;
                const __nv_bfloat16 hi = __float2bfloat16(h);
                g_hT_hi[(size_t)j * B_ + b] = hi;
                g_hT_lo[(size_t)j * B_ + b] = __float2bfloat16(h - __bfloat162float(hi));
            }
        }

        grid_barrier(++barcnt * GRID_P);
    }
}

// ---------------------------------------------------------------------------
// Phase-3 projection (packed f32x2, known good from round 3):
// out[b][t][n] = sum_k hseqT[t][k][b] * wp[n][k]
// ---------------------------------------------------------------------------
#define FMA2(acc, a, b) \
    asm("fma.rn.f32x2 %0, %1, %2, %0;" : "+l"(acc) : "l"(a), "l"(b))

__device__ __forceinline__ void unpack2(unsigned long long v, float& x, float& y) {
    asm("mov.b64 {%0, %1}, %2;" : "=f"(x), "=f"(y) : "l"(v));
}

__global__ __launch_bounds__(256) void proj_gemm(
    const float* __restrict__ hseqT,
    const float* __restrict__ wp,
    float* __restrict__ out)
{
    __shared__ float  hsm[16][64];
    __shared__ float2 ws2[16][128];

    const int tid = threadIdx.x;
    const int n0  = blockIdx.x * 128;
    const int t   = blockIdx.y;
    const float* hT = hseqT + (size_t)t * H_ * B_;

    const int bg = tid >> 5;
    const int ng = tid & 31;
    const int h_kl = tid >> 4;
    const int h_c  = (tid & 15) * 4;
    const int w_j  = tid >> 1;
    const int w_kq = (tid & 1) * 8;

    unsigned long long acc[4][4];
#pragma unroll
    for (int p = 0; p < 4; ++p)
#pragma unroll
        for (int c = 0; c < 4; ++c) acc[p][c] = 0ull;

    const float* wrow = wp + (size_t)(n0 + w_j) * 1024 + w_kq;

    for (int k0 = 0; k0 < H_; k0 += 16) {
        const float4 hv  = *(const float4*)&hT[(size_t)(k0 + h_kl) * 64 + h_c];
        const float4 wv0 = *(const float4*)&wrow[k0];
        const float4 wv1 = *(const float4*)&wrow[k0 + 4];
        __syncthreads();
        *(float4*)&hsm[h_kl][h_c] = hv;
        ws2[w_kq + 0][w_j] = make_float2(wv0.x, wv0.x);
        ws2[w_kq + 1][w_j] = make_float2(wv0.y, wv0.y);
        ws2[w_kq + 2][w_j] = make_float2(wv0.z, wv0.z);
        ws2[w_kq + 3][w_j] = make_float2(wv0.w, wv0.w);
        ws2[w_kq + 4][w_j] = make_float2(wv1.x, wv1.x);
        ws2[w_kq + 5][w_j] = make_float2(wv1.y, wv1.y);
        ws2[w_kq + 6][w_j] = make_float2(wv1.z, wv1.z);
        ws2[w_kq + 7][w_j] = make_float2(wv1.w, wv1.w);
        __syncthreads();

#pragma unroll
        for (int k = 0; k < 16; ++k) {
            const ulonglong2 A01 = *(const ulonglong2*)&hsm[k][bg * 8];
            const ulonglong2 A23 = *(const ulonglong2*)&hsm[k][bg * 8 + 4];
            const ulonglong2 W01 = *(const ulonglong2*)&ws2[k][ng * 4];
            const ulonglong2 W23 = *(const ulonglong2*)&ws2[k][ng * 4 + 2];
            FMA2(acc[0][0], A01.x, W01.x); FMA2(acc[1][0], A01.y, W01.x);
            FMA2(acc[2][0], A23.x, W01.x); FMA2(acc[3][0], A23.y, W01.x);
            FMA2(acc[0][1], A01.x, W01.y); FMA2(acc[1][1], A01.y, W01.y);
            FMA2(acc[2][1], A23.x, W01.y); FMA2(acc[3][1], A23.y, W01.y);
            FMA2(acc[0][2], A01.x, W23.x); FMA2(acc[1][2], A01.y, W23.x);
            FMA2(acc[2][2], A23.x, W23.x); FMA2(acc[3][2], A23.y, W23.x);
            FMA2(acc[0][3], A01.x, W23.y); FMA2(acc[1][3], A01.y, W23.y);
            FMA2(acc[2][3], A23.x, W23.y); FMA2(acc[3][3], A23.y, W23.y);
        }
    }

#pragma unroll
    for (int p = 0; p < 4; ++p) {
        const int b = bg * 8 + 2 * p;
#pragma unroll
        for (int c = 0; c < 4; ++c) {
            float x, y;
            unpack2(acc[p][c], x, y);
            const int n = n0 + ng * 4 + c;
            out[((size_t)b * T_ + t) * H_ + n]       = x;
            out[((size_t)(b + 1) * T_ + t) * H_ + n] = y;
        }
    }
}

// ---------------------------------------------------------------------------
// kernel_launch — 4 graph nodes, graph-capturable, allocation-free.
// Inputs: x[64,512,1024], w_ih[3072,1024], w_hh[3072,1024], w_proj[1024,1024].
// ---------------------------------------------------------------------------
extern "C" void kernel_launch(void* const* d_in, const int* in_sizes, int n_in,
                              void* d_out, int out_size) {
    const float* x      = (const float*)d_in[0];
    const float* w_ih   = (const float*)d_in[1];
    const float* w_hh   = (const float*)d_in[2];
    const float* w_proj = (const float*)d_in[3];
    float* out = (float*)d_out;

    float *gx, *hseqT;
    cudaGetSymbolAddress((void**)&gx,    g_gx);
    cudaGetSymbolAddress((void**)&hseqT, g_hseqT);

    cudaFuncSetAttribute(gru_persistent,
                         cudaFuncAttributeMaxDynamicSharedMemorySize, SM_TOTAL);

    init_kernel<<<(H_ * B_ / 2 + 255) / 256, 256>>>();

    // Phase 1: gx[t][n][b] = x @ w_ih^T
    {
        dim3 grid(G3H / 128, (B_ * T_) / 128);
        sgemm_gx<<<grid, 256>>>(x, w_ih, gx, I_);
    }

    // Phase 2: whole recurrence, ONE persistent HMMA kernel
    gru_persistent<<<GRID_P, 256, SM_TOTAL>>>(w_hh);

    // Phase 3: out[b][t][n] = hseqT[t][:][b] @ w_proj^T
    {
        dim3 grid(H_ / 128, T_);
        proj_gemm<<<grid, 256>>>(hseqT, w_proj, out);
    }
}

// round 6
// speedup vs baseline: 2.7713x; 1.0034x over previous
#include <cuda_runtime.h>
#include <cuda_bf16.h>
#include <math.h>
#include <stdint.h>

// Problem shape (fixed)
#define T_ 512
#define B_ 64
#define H_ 1024
#define I_ 1024
#define G3H 3072
#define NBLK 24
#define KSPLIT 6
#define GRID_P 144            // persistent CTAs (<=148, 1/SM => all resident)

// Dynamic smem byte offsets (sized for max klen=176, kpad=184)
#define SM_A_HI 0
#define SM_A_LO (128 * 184 * 2)                 // 47104
#define SM_B_HI (2 * 128 * 184 * 2)             // 94208
#define SM_B_LO (SM_B_HI + 176 * 72 * 2)        // 119552
#define SM_TOTAL (SM_B_LO + 176 * 72 * 2)       // 144896

// Scratch (device globals: allocation-free contract)
__device__ float g_gx[(size_t)T_ * G3H * B_];             // [t][n][b]
__device__ uint32_t g_hhl[(size_t)(T_ + 1) * H_ * B_];    // [slot][k][b]: (hi,lo) bf16 packed
__device__ float g_gh[(size_t)2 * KSPLIT * G3H * B_];     // [parity][s][n][b]
__device__ unsigned int g_rowflag[NBLK * 32];             // 1 counter / 128B
__device__ unsigned int g_sliceflag[KSPLIT * 32];

__device__ __forceinline__ uint32_t smem_u32(const void* p) {
    uint32_t a;
    asm("{ .reg .u64 t; cvta.to.shared.u64 t, %1; cvt.u32.u64 %0, t; }"
        : "=r"(a) : "l"(p));
    return a;
}
__device__ __forceinline__ void ldsm_x4(uint32_t* r, uint32_t addr) {
    asm volatile("ldmatrix.sync.aligned.m8n8.x4.shared.b16 {%0,%1,%2,%3}, [%4];"
                 : "=r"(r[0]), "=r"(r[1]), "=r"(r[2]), "=r"(r[3]) : "r"(addr));
}
__device__ __forceinline__ void ldsm_x4_t(uint32_t* r, uint32_t addr) {
    asm volatile("ldmatrix.sync.aligned.m8n8.x4.trans.shared.b16 {%0,%1,%2,%3}, [%4];"
                 : "=r"(r[0]), "=r"(r[1]), "=r"(r[2]), "=r"(r[3]) : "r"(addr));
}
__device__ __forceinline__ void mma_bf16(float* d, const uint32_t* a, const uint32_t* b) {
    asm volatile("mma.sync.aligned.m16n8k16.row.col.f32.bf16.bf16.f32 "
                 "{%0,%1,%2,%3}, {%4,%5,%6,%7}, {%8,%9}, {%0,%1,%2,%3};"
                 : "+f"(d[0]), "+f"(d[1]), "+f"(d[2]), "+f"(d[3])
                 : "r"(a[0]), "r"(a[1]), "r"(a[2]), "r"(a[3]), "r"(b[0]), "r"(b[1]));
}
__device__ __forceinline__ void flag_wait(const unsigned int* p, unsigned int target) {
    unsigned int v;
    do {
        asm volatile("ld.acquire.gpu.global.u32 %0, [%1];" : "=r"(v) : "l"(p) : "memory");
    } while (v < target);
}
__device__ __forceinline__ void flag_arrive(unsigned int* p) {
    asm volatile("red.release.gpu.global.add.u32 [%0], %1;" :: "l"(p), "r"(1u) : "memory");
}
__device__ __forceinline__ float unhl(uint32_t p) {
    return __bfloat162float(__ushort_as_bfloat16((unsigned short)(p & 0xffffu))) +
           __bfloat162float(__ushort_as_bfloat16((unsigned short)(p >> 16)));
}
__device__ __forceinline__ uint32_t packhl(float h) {
    const __nv_bfloat16 hi = __float2bfloat16(h);
    const __nv_bfloat16 lo = __float2bfloat16(h - __bfloat162float(hi));
    return (uint32_t)__bfloat16_as_ushort(hi) | ((uint32_t)__bfloat16_as_ushort(lo) << 16);
}

__global__ void init_kernel() {
    int i = blockIdx.x * blockDim.x + threadIdx.x;
    if (i < H_ * B_) g_hhl[i] = 0u;                // slot 0 = h_{-1} = 0
    if (i < NBLK * 32) g_rowflag[i] = 0u;
    if (i < KSPLIT * 32) g_sliceflag[i] = 0u;
}

// ---------------------------------------------------------------------------
// Phase-1 SGEMM-NT with scatter epilogue: gx[t][n][b] = x @ w_ih^T
// (known good from round 5)
// ---------------------------------------------------------------------------
__global__ __launch_bounds__(256) void sgemm_gx(
    const float* __restrict__ A, const float* __restrict__ B,
    float* __restrict__ C, int K)
{
    __shared__ float As[8][128];
    __shared__ float Bs[8][128];

    const int tid = threadIdx.x;
    const int r0 = blockIdx.y * 128;
    const int c0 = blockIdx.x * 128;

    const int lrow = tid >> 1;
    const int lq   = (tid & 1) * 4;

    const float* Aptr = A + (size_t)(r0 + lrow) * K + lq;
    const float* Bptr = B + (size_t)(c0 + lrow) * K + lq;

    const int mm = (tid >> 4) << 3;
    const int nn = (tid & 15) << 3;

    float acc[8][8];
#pragma unroll
    for (int i = 0; i < 8; ++i)
#pragma unroll
        for (int j = 0; j < 8; ++j) acc[i][j] = 0.0f;

    for (int k0 = 0; k0 < K; k0 += 8) {
        const float4 av = *(const float4*)(Aptr + k0);
        const float4 bv = *(const float4*)(Bptr + k0);
        __syncthreads();
        As[lq + 0][lrow] = av.x; As[lq + 1][lrow] = av.y;
        As[lq + 2][lrow] = av.z; As[lq + 3][lrow] = av.w;
        Bs[lq + 0][lrow] = bv.x; Bs[lq + 1][lrow] = bv.y;
        Bs[lq + 2][lrow] = bv.z; Bs[lq + 3][lrow] = bv.w;
        __syncthreads();

#pragma unroll
        for (int k = 0; k < 8; ++k) {
            const float4 a0 = *(const float4*)&As[k][mm];
            const float4 a1 = *(const float4*)&As[k][mm + 4];
            const float4 b0 = *(const float4*)&Bs[k][nn];
            const float4 b1 = *(const float4*)&Bs[k][nn + 4];
            const float a[8] = {a0.x, a0.y, a0.z, a0.w, a1.x, a1.y, a1.z, a1.w};
            const float b[8] = {b0.x, b0.y, b0.z, b0.w, b1.x, b1.y, b1.z, b1.w};
#pragma unroll
            for (int i = 0; i < 8; ++i)
#pragma unroll
                for (int j = 0; j < 8; ++j)
                    acc[i][j] = fmaf(a[i], b[j], acc[i][j]);
        }
    }

#pragma unroll
    for (int i = 0; i < 8; ++i) {
        const int r = r0 + mm + i;
        const int b = r >> 9;
        const int t = r & (T_ - 1);
#pragma unroll
        for (int j = 0; j < 8; ++j) {
            const int n = c0 + nn + j;
            C[((size_t)t * G3H + n) * B_ + b] = acc[i][j];
        }
    }
}

// ---------------------------------------------------------------------------
// Persistent bf16-MMA recurrence with point-to-point flag synchronization.
// Grid 144 = 24 n-blocks x 6 k-splits. Gate partitioned by k-slice so each
// column produces exactly the h-slice it stages next step.
// ---------------------------------------------------------------------------
extern __shared__ char dynsm[];

__global__ __launch_bounds__(256) void gru_persistent(
    const float* __restrict__ w_hh)   // [3072][1024]
{
    char* sm = dynsm;
    const uint32_t smem_base = smem_u32(sm);
    const int tid = threadIdx.x;
    const int wid = tid >> 5;
    const int lid = tid & 31;
    const int bid = blockIdx.x;
    const int nbk = bid % NBLK;
    const int s   = bid / NBLK;
    const int n0  = nbk * 128;
    const int kbase = (s < 4) ? s * 176 : 704 + (s - 4) * 160;
    const int klen  = (s < 4) ? 176 : 160;
    const int nkt   = klen >> 4;
    const int kpad  = klen + 8;

    // One-time: stage W slice hi/lo, rows padded to kpad
    {
        __nv_bfloat16* wsH = (__nv_bfloat16*)(sm + SM_A_HI);
        __nv_bfloat16* wsL = (__nv_bfloat16*)(sm + SM_A_LO);
        for (int i = tid; i < 128 * klen; i += 256) {
            const int row = i / klen;
            const int k   = i - row * klen;
            const float w = w_hh[(size_t)(n0 + row) * H_ + kbase + k];
            const __nv_bfloat16 hi = __float2bfloat16(w);
            wsH[row * kpad + k] = hi;
            wsL[row * kpad + k] = __float2bfloat16(w - __bfloat162float(hi));
        }
    }

    // Warp tiling + ldmatrix addresses (validated round 5)
    const int wn = wid >> 1;
    const int wb = wid & 1;
    const uint32_t aAddr0 = smem_base + SM_A_HI +
        (uint32_t)(((wn * 32 + (lid & 15)) * kpad + ((lid >> 4) << 3)) << 1);
    const uint32_t bAddr0 = smem_base + SM_B_HI +
        (uint32_t)(((((lid >> 3) & 1) * 8 + (lid & 7)) * 72 + wb * 32 + ((lid >> 4) << 3)) << 1);
    const uint32_t A_LO_OFF = SM_A_LO - SM_A_HI;
    const uint32_t B_LO_OFF = SM_B_LO - SM_B_HI;
    const uint32_t aMOff = (uint32_t)(16 * kpad * 2);

    __nv_bfloat16* hsH = (__nv_bfloat16*)(sm + SM_B_HI);
    __nv_bfloat16* hsL = (__nv_bfloat16*)(sm + SM_B_LO);

    // Gate partition: this CTA handles elements [e_lo, e_hi) of its k-slice,
    // element e -> (j = kbase + e/64, b = e%64)
    const int nelem = klen * 64;
    const int chunk = (nelem + NBLK - 1) / NBLK;
    const int e_lo = nbk * chunk;
    const int e_hi = (e_lo + chunk < nelem) ? (e_lo + chunk) : nelem;
    const int e0 = e_lo + tid;
    const int e1 = e0 + 256;
    const bool v0 = e0 < e_hi;
    const bool v1 = e1 < e_hi;
    const int j0 = kbase + (e0 >> 6), b0v = e0 & 63;
    const int j1 = kbase + (e1 >> 6), b1v = e1 & 63;
    // rowflag wait set: n-blocks covering j-range (and +1024, +2048 gates)
    const int jb_lo = (kbase + (e_lo >> 6)) >> 7;
    const int jb_hi = (kbase + ((e_hi - 1) >> 6)) >> 7;

    for (int t = 0; t < T_; ++t) {
        const int par = t & 1;

        // ---- wait: h slice s (slot t) ready
        if (tid == 0) flag_wait(&g_sliceflag[s * 32], 24u * (unsigned)t);
        __syncthreads();

        // ---- stage h slice: packed (hi,lo) -> two smem planes
        {
            const uint32_t* hp = g_hhl + (size_t)t * H_ * B_;
            for (int i = tid; i < klen * 32; i += 256) {
                const int k  = i >> 5;
                const int bp = (i & 31) << 1;
                const uint2 v = __ldcg((const uint2*)(hp + (size_t)(kbase + k) * B_ + bp));
                *(uint32_t*)&hsH[k * 72 + bp] = __byte_perm(v.x, v.y, 0x5410);
                *(uint32_t*)&hsL[k * 72 + bp] = __byte_perm(v.x, v.y, 0x7632);
            }
        }
        __syncthreads();

        // ---- prefetch gx gate operands (independent of h; hides DRAM latency)
        float gr0 = 0.f, gz0 = 0.f, gn0 = 0.f, gr1 = 0.f, gz1 = 0.f, gn1 = 0.f;
        {
            const float* gxt = g_gx + (size_t)t * G3H * B_;
            if (v0) {
                gr0 = gxt[(size_t)j0 * B_ + b0v];
                gz0 = gxt[(size_t)(1024 + j0) * B_ + b0v];
                gn0 = gxt[(size_t)(2048 + j0) * B_ + b0v];
            }
            if (v1) {
                gr1 = gxt[(size_t)j1 * B_ + b1v];
                gz1 = gxt[(size_t)(1024 + j1) * B_ + b1v];
                gn1 = gxt[(size_t)(2048 + j1) * B_ + b1v];
            }
        }

        // ---- mainloop: 3 HMMA passes per k16 chunk
        float d[2][4][4];
#pragma unroll
        for (int m = 0; m < 2; ++m)
#pragma unroll
            for (int nt = 0; nt < 4; ++nt)
#pragma unroll
                for (int q = 0; q < 4; ++q) d[m][nt][q] = 0.0f;

        for (int kc = 0; kc < nkt; ++kc) {
            uint32_t aH0[4], aH1[4], aL0[4], aL1[4], bh[8], bl[8];
            const uint32_t aA = aAddr0 + (uint32_t)(kc * 32);
            const uint32_t bA = bAddr0 + (uint32_t)(kc * 2304);
            ldsm_x4(aH0, aA);
            ldsm_x4(aH1, aA + aMOff);
            ldsm_x4(aL0, aA + A_LO_OFF);
            ldsm_x4(aL1, aA + A_LO_OFF + aMOff);
            ldsm_x4_t(bh,     bA);
            ldsm_x4_t(bh + 4, bA + 32);
            ldsm_x4_t(bl,     bA + B_LO_OFF);
            ldsm_x4_t(bl + 4, bA + B_LO_OFF + 32);

#pragma unroll
            for (int m = 0; m < 2; ++m)
#pragma unroll
                for (int nt = 0; nt < 4; ++nt)
                    mma_bf16(d[m][nt], m ? aH1 : aH0, &bh[nt * 2]);
#pragma unroll
            for (int m = 0; m < 2; ++m)
#pragma unroll
                for (int nt = 0; nt < 4; ++nt)
                    mma_bf16(d[m][nt], m ? aH1 : aH0, &bl[nt * 2]);
#pragma unroll
            for (int m = 0; m < 2; ++m)
#pragma unroll
                for (int nt = 0; nt < 4; ++nt)
                    mma_bf16(d[m][nt], m ? aL1 : aL0, &bh[nt * 2]);
        }

        // ---- epilogue: D(n,b) -> g_gh[par][s][n][b], then release row flag
        {
            float* gh = g_gh + ((size_t)par * KSPLIT + s) * G3H * B_;
            const int g = lid >> 2;
            const int q = lid & 3;
#pragma unroll
            for (int m = 0; m < 2; ++m)
#pragma unroll
                for (int nt = 0; nt < 4; ++nt) {
                    const int n = n0 + wn * 32 + m * 16 + g;
                    const int b = wb * 32 + nt * 8 + q * 2;
                    *(float2*)&gh[(size_t)n * B_ + b] =
                        make_float2(d[m][nt][0], d[m][nt][1]);
                    *(float2*)&gh[(size_t)(n + 8) * B_ + b] =
                        make_float2(d[m][nt][2], d[m][nt][3]);
                }
        }
        __syncthreads();
        if (tid == 0) flag_arrive(&g_rowflag[nbk * 32]);

        // ---- wait for the gh rows this CTA's gate slice needs
        if (tid == 0) {
            const unsigned tgt = 6u * (unsigned)(t + 1);
            for (int jb = jb_lo; jb <= jb_hi; ++jb) {
                flag_wait(&g_rowflag[jb * 32], tgt);
                flag_wait(&g_rowflag[(jb + 8) * 32], tgt);
                flag_wait(&g_rowflag[(jb + 16) * 32], tgt);
            }
        }
        __syncthreads();

        // ---- gate: reduce 6 split partials, activations, write h slot t+1
        {
            const float* ghp = g_gh + (size_t)par * KSPLIT * G3H * B_;
            const uint32_t* hprev = g_hhl + (size_t)t * H_ * B_;
            uint32_t* hout = g_hhl + (size_t)(t + 1) * H_ * B_;
            if (v0) {
                float sr = 0.f, sz = 0.f, sn = 0.f;
#pragma unroll
                for (int ss = 0; ss < KSPLIT; ++ss) {
                    const float* p = ghp + (size_t)ss * G3H * B_;
                    sr += __ldcg(p + (size_t)j0 * B_ + b0v);
                    sz += __ldcg(p + (size_t)(1024 + j0) * B_ + b0v);
                    sn += __ldcg(p + (size_t)(2048 + j0) * B_ + b0v);
                }
                const float r = 1.0f / (1.0f + expf(-(gr0 + sr)));
                const float z = 1.0f / (1.0f + expf(-(gz0 + sz)));
                const float n = tanhf(gn0 + r * sn);
                const float hp = unhl(hprev[(size_t)j0 * B_ + b0v]);
                hout[(size_t)j0 * B_ + b0v] = packhl((1.0f - z) * n + z * hp);
            }
            if (v1) {
                float sr = 0.f, sz = 0.f, sn = 0.f;
#pragma unroll
                for (int ss = 0; ss < KSPLIT; ++ss) {
                    const float* p = ghp + (size_t)ss * G3H * B_;
                    sr += __ldcg(p + (size_t)j1 * B_ + b1v);
                    sz += __ldcg(p + (size_t)(1024 + j1) * B_ + b1v);
                    sn += __ldcg(p + (size_t)(2048 + j1) * B_ + b1v);
                }
                const float r = 1.0f / (1.0f + expf(-(gr1 + sr)));
                const float z = 1.0f / (1.0f + expf(-(gz1 + sz)));
                const float n = tanhf(gn1 + r * sn);
                const float hp = unhl(hprev[(size_t)j1 * B_ + b1v]);
                hout[(size_t)j1 * B_ + b1v] = packhl((1.0f - z) * n + z * hp);
            }
        }
        __syncthreads();
        if (tid == 0) flag_arrive(&g_sliceflag[s * 32]);
    }
}

// ---------------------------------------------------------------------------
// Phase-3 projection (packed f32x2): reads packed (hi,lo) h state.
// out[b][t][n] = sum_k h[t][k][b] * wp[n][k]
// ---------------------------------------------------------------------------
#define FMA2(acc, a, b) \
    asm("fma.rn.f32x2 %0, %1, %2, %0;" : "+l"(acc) : "l"(a), "l"(b))

__device__ __forceinline__ void unpack2(unsigned long long v, float& x, float& y) {
    asm("mov.b64 {%0, %1}, %2;" : "=f"(x), "=f"(y) : "l"(v));
}

__global__ __launch_bounds__(256) void proj_gemm(
    const uint32_t* __restrict__ hhl,
    const float* __restrict__ wp,
    float* __restrict__ out)
{
    __shared__ float  hsm[16][64];
    __shared__ float2 ws2[16][128];

    const int tid = threadIdx.x;
    const int n0  = blockIdx.x * 128;
    const int t   = blockIdx.y;
    const uint32_t* hT = hhl + (size_t)(t + 1) * H_ * B_;

    const int bg = tid >> 5;
    const int ng = tid & 31;
    const int h_kl = tid >> 4;
    const int h_c  = (tid & 15) * 4;
    const int w_j  = tid >> 1;
    const int w_kq = (tid & 1) * 8;

    unsigned long long acc[4][4];
#pragma unroll
    for (int p = 0; p < 4; ++p)
#pragma unroll
        for (int c = 0; c < 4; ++c) acc[p][c] = 0ull;

    const float* wrow = wp + (size_t)(n0 + w_j) * 1024 + w_kq;

    for (int k0 = 0; k0 < H_; k0 += 16) {
        const uint4 hv = *(const uint4*)&hT[(size_t)(k0 + h_kl) * 64 + h_c];
        const float4 wv0 = *(const float4*)&wrow[k0];
        const float4 wv1 = *(const float4*)&wrow[k0 + 4];
        __syncthreads();
        hsm[h_kl][h_c + 0] = unhl(hv.x);
        hsm[h_kl][h_c + 1] = unhl(hv.y);
        hsm[h_kl][h_c + 2] = unhl(hv.z);
        hsm[h_kl][h_c + 3] = unhl(hv.w);
        ws2[w_kq + 0][w_j] = make_float2(wv0.x, wv0.x);
        ws2[w_kq + 1][w_j] = make_float2(wv0.y, wv0.y);
        ws2[w_kq + 2][w_j] = make_float2(wv0.z, wv0.z);
        ws2[w_kq + 3][w_j] = make_float2(wv0.w, wv0.w);
        ws2[w_kq + 4][w_j] = make_float2(wv1.x, wv1.x);
        ws2[w_kq + 5][w_j] = make_float2(wv1.y, wv1.y);
        ws2[w_kq + 6][w_j] = make_float2(wv1.z, wv1.z);
        ws2[w_kq + 7][w_j] = make_float2(wv1.w, wv1.w);
        __syncthreads();

#pragma unroll
        for (int k = 0; k < 16; ++k) {
            const ulonglong2 A01 = *(const ulonglong2*)&hsm[k][bg * 8];
            const ulonglong2 A23 = *(const ulonglong2*)&hsm[k][bg * 8 + 4];
            const ulonglong2 W01 = *(const ulonglong2*)&ws2[k][ng * 4];
            const ulonglong2 W23 = *(const ulonglong2*)&ws2[k][ng * 4 + 2];
            FMA2(acc[0][0], A01.x, W01.x); FMA2(acc[1][0], A01.y, W01.x);
            FMA2(acc[2][0], A23.x, W01.x); FMA2(acc[3][0], A23.y, W01.x);
            FMA2(acc[0][1], A01.x, W01.y); FMA2(acc[1][1], A01.y, W01.y);
            FMA2(acc[2][1], A23.x, W01.y); FMA2(acc[3][1], A23.y, W01.y);
            FMA2(acc[0][2], A01.x, W23.x); FMA2(acc[1][2], A01.y, W23.x);
            FMA2(acc[2][2], A23.x, W23.x); FMA2(acc[3][2], A23.y, W23.x);
            FMA2(acc[0][3], A01.x, W23.y); FMA2(acc[1][3], A01.y, W23.y);
            FMA2(acc[2][3], A23.x, W23.y); FMA2(acc[3][3], A23.y, W23.y);
        }
    }

#pragma unroll
    for (int p = 0; p < 4; ++p) {
        const int b = bg * 8 + 2 * p;
#pragma unroll
        for (int c = 0; c < 4; ++c) {
            float x, y;
            unpack2(acc[p][c], x, y);
            const int n = n0 + ng * 4 + c;
            out[((size_t)b * T_ + t) * H_ + n]       = x;
            out[((size_t)(b + 1) * T_ + t) * H_ + n] = y;
        }
    }
}

// ---------------------------------------------------------------------------
// kernel_launch — 4 graph nodes, graph-capturable, allocation-free.
// Inputs: x[64,512,1024], w_ih[3072,1024], w_hh[3072,1024], w_proj[1024,1024].
// ---------------------------------------------------------------------------
extern "C" void kernel_launch(void* const* d_in, const int* in_sizes, int n_in,
                              void* d_out, int out_size) {
    const float* x      = (const float*)d_in[0];
    const float* w_ih   = (const float*)d_in[1];
    const float* w_hh   = (const float*)d_in[2];
    const float* w_proj = (const float*)d_in[3];
    float* out = (float*)d_out;

    float* gx;
    uint32_t* hhl;
    cudaGetSymbolAddress((void**)&gx,  g_gx);
    cudaGetSymbolAddress((void**)&hhl, g_hhl);

    cudaFuncSetAttribute(gru_persistent,
                         cudaFuncAttributeMaxDynamicSharedMemorySize, SM_TOTAL);

    init_kernel<<<(H_ * B_ + 255) / 256, 256>>>();

    // Phase 1: gx[t][n][b] = x @ w_ih^T
    {
        dim3 grid(G3H / 128, (B_ * T_) / 128);
        sgemm_gx<<<grid, 256>>>(x, w_ih, gx, I_);
    }

    // Phase 2: whole recurrence, ONE persistent flag-synced HMMA kernel
    gru_persistent<<<GRID_P, 256, SM_TOTAL>>>(w_hh);

    // Phase 3: out[b][t][n] = h[t] @ w_proj^T
    {
        dim3 grid(H_ / 128, T_);
        proj_gemm<<<grid, 256>>>(hhl, w_proj, out);
    }
}